// round 2
// baseline (speedup 1.0000x reference)
#include <cuda_runtime.h>
#include <cuda_bf16.h>

// ---------------------------------------------------------------------------
// BM25, vocab-collapsed:
//   score = sum_v hq[v] * (hq[v]/(K3+hq[v])) * (K1*hp[v]/(hp[v]+C1)) * idf(DF[v])
//   out   = sigmoid(score)
// Pass B: u32 histograms of both id rows via global RED (SM-side floor:
//         ~1.29 cyc/lane spread-addr => ~81us for 16.7M increments).
// Pass C: per-vocab scoring, re-zeroes histograms, last block finalizes.
// ---------------------------------------------------------------------------

#define VOCAB_MAX (1 << 20)   // 1,048,576 >= 1,000,000

__device__ unsigned g_hq[VOCAB_MAX];   // zero-init; every launch restores zeros
__device__ unsigned g_hp[VOCAB_MAX];
__device__ float    g_acc;             // score accumulator (reset by last block)
__device__ unsigned g_done;            // block-completion counter (reset by last block)

// ---------------- Pass B: histogram (u32 RED) ----------------
__global__ __launch_bounds__(256)
void bm25_hist(const int4* __restrict__ ids4, int n4, int half4, unsigned vocab) {
    int stride = gridDim.x * blockDim.x;
    for (int i = blockIdx.x * blockDim.x + threadIdx.x; i < n4; i += stride) {
        int4 t = ids4[i];
        unsigned* tbl = (i < half4) ? g_hq : g_hp;   // int4 never straddles rows (L%4==0)
        if ((unsigned)t.x < vocab) atomicAdd(tbl + t.x, 1u);
        if ((unsigned)t.y < vocab) atomicAdd(tbl + t.y, 1u);
        if ((unsigned)t.z < vocab) atomicAdd(tbl + t.z, 1u);
        if ((unsigned)t.w < vocab) atomicAdd(tbl + t.w, 1u);
    }
}

// ---------------- Pass C: per-vocab scoring + finalize ----------------
__device__ __forceinline__ float bm25_term(unsigned cqi, unsigned cpi, float d, float C1) {
    const float K1 = 1.2f;
    const float K3 = 8.0f;
    float cq = (float)cqi;
    float cp = (float)cpi;
    // idf = log2((N-d+0.5)/(d+0.5)) ~= LOG2_NP - d*CT - log2(d+0.5)  (d/N<=1.1e-3)
    const float LOG2_NP = 23.0759147f;     // log2(8841823.5)
    const float CT      = 1.631670e-7f;    // 1/((N+0.5)*ln2)
    float idf = (LOG2_NP - d * CT) - __log2f(d + 0.5f);
    float num = cq * cq * (K1 * cp);
    float den = (K3 + cq) * (cp + C1);
    return __fdividef(num, den) * idf;     // exact 0 when cq==0 or cp==0
}

__global__ __launch_bounds__(256)
void bm25_score(const float4* __restrict__ df4, int n4, float C1,
                float* __restrict__ out) {
    uint4* hq4 = reinterpret_cast<uint4*>(g_hq);
    uint4* hp4 = reinterpret_cast<uint4*>(g_hp);
    const uint4 z4 = make_uint4(0u, 0u, 0u, 0u);

    float sum = 0.f;
    int stride = gridDim.x * blockDim.x;
    for (int i = blockIdx.x * blockDim.x + threadIdx.x; i < n4; i += stride) {
        uint4 q = hq4[i];  hq4[i] = z4;    // read + restore zeros (L2-resident)
        uint4 p = hp4[i];  hp4[i] = z4;
        float4 d = df4[i];
        sum += bm25_term(q.x, p.x, d.x, C1);
        sum += bm25_term(q.y, p.y, d.y, C1);
        sum += bm25_term(q.z, p.z, d.z, C1);
        sum += bm25_term(q.w, p.w, d.w, C1);
    }

    // warp reduce
    #pragma unroll
    for (int off = 16; off > 0; off >>= 1)
        sum += __shfl_down_sync(0xFFFFFFFFu, sum, off);

    __shared__ float wsum[8];
    int lane = threadIdx.x & 31;
    int wid  = threadIdx.x >> 5;
    if (lane == 0) wsum[wid] = sum;
    __syncthreads();

    if (threadIdx.x == 0) {
        float s = 0.f;
        #pragma unroll
        for (int w = 0; w < 8; w++) s += wsum[w];
        atomicAdd(&g_acc, s);
        __threadfence();
        unsigned ticket = atomicAdd(&g_done, 1u);
        if (ticket == gridDim.x - 1) {               // last block finalizes
            float sc = g_acc;
            out[0] = 1.0f / (1.0f + __expf(-sc));
            g_acc  = 0.f;                            // restore invariants
            g_done = 0u;
        }
    }
}

// ---------------------------------------------------------------------------
extern "C" void kernel_launch(void* const* d_in, const int* in_sizes, int n_in,
                              void* d_out, int out_size) {
    const int*   ids = (const int*)d_in[0];   // [2, L] int32
    // d_in[1] = masks (unused by reference forward)
    const float* DF  = (const float*)d_in[2]; // [vocab] float32

    int twoL  = in_sizes[0];
    int L     = twoL >> 1;
    int vocab = in_sizes[2];

    float Ld = (float)L;
    float C1 = 1.2f * (1.0f - 0.75f + 0.75f * Ld / 56.0f);

    // 1184 blocks x 256 = 303,104 threads: exactly one resident wave (8 CTAs/SM)
    bm25_hist<<<1184, 256>>>((const int4*)ids, twoL >> 2, L >> 2, (unsigned)vocab);
    bm25_score<<<592, 256>>>((const float4*)DF, vocab >> 2, C1, (float*)d_out);
}

// round 3
// speedup vs baseline: 1.0212x; 1.0212x over previous
#include <cuda_runtime.h>
#include <cuda_bf16.h>

// ---------------------------------------------------------------------------
// BM25, vocab-collapsed:
//   score = sum_v hq[v] * (hq[v]/(K3+hq[v])) * (K1*hp[v]/(hp[v]+C1)) * idf(DF[v])
//   out   = sigmoid(score)
// Pass B: u32 histograms via global RED (u32 measured faster than f32 at LTS;
//         at the ~1.29 cyc/lane SM-side REDG floor => ~74us for 16.7M incs).
// Pass C: per-vocab scoring, one element-quad per thread, re-zeroes tables.
// Pass D: tiny finalize (sigmoid + accumulator reset). No fences, no tickets.
// ---------------------------------------------------------------------------

#define VOCAB_MAX (1 << 20)   // 1,048,576 >= 1,000,000

__device__ unsigned g_hq[VOCAB_MAX];   // zero-init; every launch restores zeros
__device__ unsigned g_hp[VOCAB_MAX];
__device__ float    g_acc;             // score accumulator; reset by finalize

// ---------------- Pass B: histogram (u32 RED) ----------------
__global__ __launch_bounds__(256)
void bm25_hist(const int4* __restrict__ ids4, int n4, int half4, unsigned vocab) {
    int stride = gridDim.x * blockDim.x;
    for (int i = blockIdx.x * blockDim.x + threadIdx.x; i < n4; i += stride) {
        int4 t = ids4[i];
        unsigned* tbl = (i < half4) ? g_hq : g_hp;   // int4 never straddles rows (L%4==0)
        if ((unsigned)t.x < vocab) atomicAdd(tbl + t.x, 1u);
        if ((unsigned)t.y < vocab) atomicAdd(tbl + t.y, 1u);
        if ((unsigned)t.z < vocab) atomicAdd(tbl + t.z, 1u);
        if ((unsigned)t.w < vocab) atomicAdd(tbl + t.w, 1u);
    }
}

// ---------------- Pass C: per-vocab scoring ----------------
__device__ __forceinline__ float bm25_term(unsigned cqi, unsigned cpi, float d, float C1) {
    const float K1 = 1.2f;
    const float K3 = 8.0f;
    float cq = (float)cqi;
    float cp = (float)cpi;
    // idf = log2((N-d+0.5)/(d+0.5)) ~= LOG2_NP - d*CT - log2(d+0.5)  (d/N<=1.1e-3)
    const float LOG2_NP = 23.0759147f;     // log2(8841823.5)
    const float CT      = 1.631670e-7f;    // 1/((N+0.5)*ln2)
    float idf = (LOG2_NP - d * CT) - __log2f(d + 0.5f);
    float num = cq * cq * (K1 * cp);
    float den = (K3 + cq) * (cp + C1);
    return __fdividef(num, den) * idf;     // exact 0 when cq==0 or cp==0
}

__global__ __launch_bounds__(256)
void bm25_score(const float4* __restrict__ df4, int n4, float C1) {
    uint4* hq4 = reinterpret_cast<uint4*>(g_hq);
    uint4* hp4 = reinterpret_cast<uint4*>(g_hp);
    const uint4 z4 = make_uint4(0u, 0u, 0u, 0u);

    float sum = 0.f;
    int i = blockIdx.x * blockDim.x + threadIdx.x;   // exactly one quad per thread
    if (i < n4) {
        uint4  q = hq4[i];
        uint4  p = hp4[i];
        float4 d = df4[i];
        hq4[i] = z4;                        // restore zeros (L2-resident writeback)
        hp4[i] = z4;
        sum += bm25_term(q.x, p.x, d.x, C1);
        sum += bm25_term(q.y, p.y, d.y, C1);
        sum += bm25_term(q.z, p.z, d.z, C1);
        sum += bm25_term(q.w, p.w, d.w, C1);
    }

    // warp reduce
    #pragma unroll
    for (int off = 16; off > 0; off >>= 1)
        sum += __shfl_down_sync(0xFFFFFFFFu, sum, off);

    __shared__ float wsum[8];
    int lane = threadIdx.x & 31;
    int wid  = threadIdx.x >> 5;
    if (lane == 0) wsum[wid] = sum;
    __syncthreads();
    if (threadIdx.x == 0) {
        float s = 0.f;
        #pragma unroll
        for (int w = 0; w < 8; w++) s += wsum[w];
        atomicAdd(&g_acc, s);               // blocks finish async => no contention
    }
}

// ---------------- Pass D: sigmoid + reset (+ vocab%4 tail) ----------------
__global__ void bm25_finalize(float* __restrict__ out, int tail_base, int tail_n,
                              const float* __restrict__ DF, float C1) {
    float s = g_acc;
    for (int k = 0; k < tail_n; k++) {      // generality; tail_n == 0 for vocab=1M
        int v = tail_base + k;
        s += bm25_term(g_hq[v], g_hp[v], DF[v], C1);
        g_hq[v] = 0u;
        g_hp[v] = 0u;
    }
    g_acc = 0.f;                            // restore invariant for next replay
    out[0] = 1.0f / (1.0f + __expf(-s));
}

// ---------------------------------------------------------------------------
extern "C" void kernel_launch(void* const* d_in, const int* in_sizes, int n_in,
                              void* d_out, int out_size) {
    const int*   ids = (const int*)d_in[0];   // [2, L] int32
    // d_in[1] = masks (unused by reference forward)
    const float* DF  = (const float*)d_in[2]; // [vocab] float32

    int twoL  = in_sizes[0];
    int L     = twoL >> 1;
    int vocab = in_sizes[2];

    float Ld = (float)L;
    float C1 = 1.2f * (1.0f - 0.75f + 0.75f * Ld / 56.0f);

    int n4 = vocab >> 2;
    int tail_base = n4 << 2;
    int tail_n = vocab - tail_base;

    // hist: 1184 blocks = exactly one resident wave (8 CTAs/SM on 148 SMs)
    bm25_hist<<<1184, 256>>>((const int4*)ids, twoL >> 2, L >> 2, (unsigned)vocab);
    // score: one quad per thread, fully parallel single wave
    bm25_score<<<(n4 + 255) / 256, 256>>>((const float4*)DF, n4, C1);
    bm25_finalize<<<1, 1>>>((float*)d_out, tail_base, tail_n, DF, C1);
}